// round 1
// baseline (speedup 1.0000x reference)
#include <cuda_runtime.h>
#include <cuda_bf16.h>

#define NOBJ 20000
#define NTRI 100000
#define DIM  512   // D == H == 512

// ---------------- static device scratch (allocation-free) ----------------
__device__ float g_h[(size_t)NTRI * DIM];        // 205 MB: h = relu(cur_t @ W1^T)
__device__ float g_pooled[(size_t)NOBJ * DIM];   // 41 MB
__device__ float g_g[(size_t)NOBJ * DIM];        // 41 MB: g = relu(pooled @ V1^T)
__device__ float g_counts[NOBJ];

// ---------------- small kernels ----------------
__global__ void zero_kernel(float* pooled, float* counts) {
    int i = blockIdx.x * blockDim.x + threadIdx.x;
    if (i < NOBJ * DIM) pooled[i] = 0.f;
    if (i < NOBJ) counts[i] = 0.f;
}

__global__ void count_kernel(const int* __restrict__ edges, float* counts) {
    int i = blockIdx.x * blockDim.x + threadIdx.x;
    if (i < NTRI) {
        atomicAdd(&counts[edges[2 * i]], 1.f);
        atomicAdd(&counts[edges[2 * i + 1]], 1.f);
    }
}

__global__ void normalize_kernel(float* pooled, const float* __restrict__ counts) {
    int i = blockIdx.x * blockDim.x + threadIdx.x;
    if (i < NOBJ * DIM) {
        float c = counts[i >> 9];           // i / 512
        pooled[i] *= (1.f / fmaxf(c, 1.f));
    }
}

// ---------------- tiled SGEMM: C[M,N] = epilogue(A[M,K] @ B[N,K]^T + bias) ----------------
// MA: 0 = plain A, 1 = gather-concat [obj[s] | pred | obj[o]] (K must be 3*DIM)
// ME: 0 = C[r,c] = relu(v)
//     1 = C[r,c] += v                  (residual add, no relu)
//     2 = split: v=relu(v); c<512 -> atomicAdd pooled[s_idx[r]];
//         512<=c<1024 -> outp[r, c-512] = v; else atomicAdd pooled[o_idx[r]]
constexpr int BM = 128, BN = 128, BK = 8, TM = 8, TN = 8;

template <int MA, int ME>
__global__ void __launch_bounds__(256, 2)
gemm_kernel(const float* __restrict__ A, const float* __restrict__ B,
            const float* __restrict__ bias, float* __restrict__ C,
            int M, int N, int K,
            const float* __restrict__ objv, const float* __restrict__ predv,
            const int* __restrict__ edges,
            float* __restrict__ pooled, float* __restrict__ outp)
{
    __shared__ __align__(16) float As[BK][BM + 4];
    __shared__ __align__(16) float Bs[BK][BN + 4];

    const int tid = threadIdx.x;
    const int tx = tid & 15;          // 0..15 -> column group
    const int ty = tid >> 4;          // 0..15 -> row group
    const int rowBlock = blockIdx.y * BM;
    const int colBlock = blockIdx.x * BN;

    // tile-load mapping: each thread loads one float4 of A and one of B per k-step
    const int aRow = tid >> 1;              // 0..127
    const int aCol = (tid & 1) * 4;         // 0 or 4
    const int bRow = tid >> 1;
    const int bCol = (tid & 1) * 4;

    float acc[TM][TN];
#pragma unroll
    for (int i = 0; i < TM; i++)
#pragma unroll
        for (int j = 0; j < TN; j++) acc[i][j] = 0.f;

    for (int k0 = 0; k0 < K; k0 += BK) {
        // ---- global loads into registers ----
        float4 av = make_float4(0.f, 0.f, 0.f, 0.f);
        {
            int gr = rowBlock + aRow;
            if (gr < M) {
                if (MA == 0) {
                    av = *reinterpret_cast<const float4*>(&A[(size_t)gr * K + k0 + aCol]);
                } else {
                    int k = k0 + aCol;  // all 4 elems stay inside one 512-region
                    const float* src;
                    if (k < DIM)            src = &objv[(size_t)edges[2 * gr] * DIM + k];
                    else if (k < 2 * DIM)   src = &predv[(size_t)gr * DIM + (k - DIM)];
                    else                    src = &objv[(size_t)edges[2 * gr + 1] * DIM + (k - 2 * DIM)];
                    av = *reinterpret_cast<const float4*>(src);
                }
            }
        }
        float4 bv = *reinterpret_cast<const float4*>(&B[(size_t)(colBlock + bRow) * K + k0 + bCol]);

        __syncthreads();   // previous compute done before overwriting smem
        As[aCol + 0][aRow] = av.x;
        As[aCol + 1][aRow] = av.y;
        As[aCol + 2][aRow] = av.z;
        As[aCol + 3][aRow] = av.w;
        Bs[bCol + 0][bRow] = bv.x;
        Bs[bCol + 1][bRow] = bv.y;
        Bs[bCol + 2][bRow] = bv.z;
        Bs[bCol + 3][bRow] = bv.w;
        __syncthreads();

        // ---- compute ----
#pragma unroll
        for (int k = 0; k < BK; k++) {
            float a[TM], b[TN];
            *reinterpret_cast<float4*>(&a[0]) = *reinterpret_cast<const float4*>(&As[k][ty * TM]);
            *reinterpret_cast<float4*>(&a[4]) = *reinterpret_cast<const float4*>(&As[k][ty * TM + 4]);
            *reinterpret_cast<float4*>(&b[0]) = *reinterpret_cast<const float4*>(&Bs[k][tx * TN]);
            *reinterpret_cast<float4*>(&b[4]) = *reinterpret_cast<const float4*>(&Bs[k][tx * TN + 4]);
#pragma unroll
            for (int i = 0; i < TM; i++)
#pragma unroll
                for (int j = 0; j < TN; j++)
                    acc[i][j] = fmaf(a[i], b[j], acc[i][j]);
        }
    }

    // ---- epilogue ----
#pragma unroll
    for (int i = 0; i < TM; i++) {
        int r = rowBlock + ty * TM + i;
        if (r >= M) continue;
        int si = 0, oi = 0;
        if (ME == 2) { si = edges[2 * r]; oi = edges[2 * r + 1]; }
#pragma unroll
        for (int j = 0; j < TN; j++) {
            int c = colBlock + tx * TN + j;
            float v = acc[i][j] + bias[c];
            if (ME == 0) {
                C[(size_t)r * N + c] = fmaxf(v, 0.f);
            } else if (ME == 1) {
                C[(size_t)r * N + c] += v;
            } else {
                v = fmaxf(v, 0.f);
                if (c < DIM)            atomicAdd(&pooled[(size_t)si * DIM + c], v);
                else if (c < 2 * DIM)   outp[(size_t)r * DIM + (c - DIM)] = v;
                else                    atomicAdd(&pooled[(size_t)oi * DIM + (c - 2 * DIM)], v);
            }
        }
    }
}

// ---------------- launcher ----------------
extern "C" void kernel_launch(void* const* d_in, const int* in_sizes, int n_in,
                              void* d_out, int out_size)
{
    const float* objv    = (const float*)d_in[0];
    const float* predv   = (const float*)d_in[1];
    const int*   edges   = (const int*)  d_in[2];
    const float* W1      = (const float*)d_in[3];
    const float* b1      = (const float*)d_in[4];
    const float* W2      = (const float*)d_in[5];
    const float* b2      = (const float*)d_in[6];
    const float* V1      = (const float*)d_in[7];
    const float* c1      = (const float*)d_in[8];
    const float* V2      = (const float*)d_in[9];
    const float* c2      = (const float*)d_in[10];
    const float* P_obj   = (const float*)d_in[11];
    const float* pb_obj  = (const float*)d_in[12];
    const float* P_pred  = (const float*)d_in[13];
    const float* pb_pred = (const float*)d_in[14];

    float *hp, *pooledp, *gp, *countsp;
    cudaGetSymbolAddress((void**)&hp,      g_h);
    cudaGetSymbolAddress((void**)&pooledp, g_pooled);
    cudaGetSymbolAddress((void**)&gp,      g_g);
    cudaGetSymbolAddress((void**)&countsp, g_counts);

    float* out_obj = (float*)d_out;                          // [20000, 512]
    float* out_p   = (float*)d_out + (size_t)NOBJ * DIM;     // [100000, 512]

    // 0) zero accumulators (must be per-replay: graph replays re-accumulate)
    zero_kernel<<<(NOBJ * DIM + 255) / 256, 256>>>(pooledp, countsp);
    // 1) counts
    count_kernel<<<(NTRI + 255) / 256, 256>>>(edges, countsp);

    // 2) G1: h = relu([obj[s]|pred|obj[o]] @ W1^T + b1)     (100k x 512 x 1536)
    {
        dim3 grid(DIM / BN, (NTRI + BM - 1) / BM);
        gemm_kernel<1, 0><<<grid, 256>>>(nullptr, W1, b1, hp,
                                         NTRI, DIM, 3 * DIM,
                                         objv, predv, edges, nullptr, nullptr);
    }
    // 3) G2: new_t = relu(h @ W2^T + b2); split into pooled atomics + new_p store
    {
        dim3 grid((3 * DIM) / BN, (NTRI + BM - 1) / BM);
        gemm_kernel<0, 2><<<grid, 256>>>(hp, W2, b2, nullptr,
                                         NTRI, 3 * DIM, DIM,
                                         nullptr, nullptr, edges, pooledp, out_p);
    }
    // 4) pooled /= max(counts, 1)
    normalize_kernel<<<(NOBJ * DIM + 255) / 256, 256>>>(pooledp, countsp);

    dim3 gridObj(DIM / BN, (NOBJ + BM - 1) / BM);
    // 5) G3: g = relu(pooled @ V1^T + c1)
    gemm_kernel<0, 0><<<gridObj, 256>>>(pooledp, V1, c1, gp,
                                        NOBJ, DIM, DIM,
                                        nullptr, nullptr, nullptr, nullptr, nullptr);
    // 6) G4: out_obj = relu(g @ V2^T + c2)
    gemm_kernel<0, 0><<<gridObj, 256>>>(gp, V2, c2, out_obj,
                                        NOBJ, DIM, DIM,
                                        nullptr, nullptr, nullptr, nullptr, nullptr);
    // 7) G5: out_obj += obj @ P_obj^T + pb_obj
    gemm_kernel<0, 1><<<gridObj, 256>>>(objv, P_obj, pb_obj, out_obj,
                                        NOBJ, DIM, DIM,
                                        nullptr, nullptr, nullptr, nullptr, nullptr);
    // 8) G6: out_p += pred @ P_pred^T + pb_pred
    {
        dim3 grid(DIM / BN, (NTRI + BM - 1) / BM);
        gemm_kernel<0, 1><<<grid, 256>>>(predv, P_pred, pb_pred, out_p,
                                         NTRI, DIM, DIM,
                                         nullptr, nullptr, nullptr, nullptr, nullptr);
    }
}

// round 3
// speedup vs baseline: 5.1891x; 5.1891x over previous
#include <cuda_runtime.h>
#include <cuda_fp16.h>
#include <cstdint>

#define NOBJ 20000
#define NTRI 100000
#define DIM  512

// ---------------- static device scratch (allocation-free) ----------------
__device__ __half g_hh[(size_t)NTRI * DIM];      // h = relu(...) in fp16
__device__ float  g_pooled[(size_t)NOBJ * DIM];  // fp32 pooled accumulator
__device__ __half g_poolh[(size_t)NOBJ * DIM];   // pooled normalized, fp16
__device__ __half g_gh[(size_t)NOBJ * DIM];      // g = relu(...) fp16
__device__ float  g_counts[NOBJ];
__device__ __half g_objh[(size_t)NOBJ * DIM];
__device__ __half g_predh[(size_t)NTRI * DIM];
__device__ __half g_W1h[512 * 1536];
__device__ __half g_W2h[1536 * 512];
__device__ __half g_V1h[512 * 512];
__device__ __half g_V2h[512 * 512];
__device__ __half g_Poh[512 * 512];
__device__ __half g_Pph[512 * 512];

// ---------------- helpers ----------------
__device__ __forceinline__ uint32_t smem_u32(const void* p) {
    uint32_t a;
    asm("{ .reg .u64 t; cvta.to.shared.u64 t, %1; cvt.u32.u64 %0, t; }" : "=r"(a) : "l"(p));
    return a;
}
__device__ __forceinline__ void cp16(void* sdst, const void* gsrc) {
    uint32_t d = smem_u32(sdst);
    asm volatile("cp.async.cg.shared.global [%0], [%1], 16;" :: "r"(d), "l"(gsrc) : "memory");
}
__device__ __forceinline__ void cp_commit() {
    asm volatile("cp.async.commit_group;" ::: "memory");
}
__device__ __forceinline__ void mma16816(float* d, const uint32_t* a, const uint32_t* b) {
    asm volatile(
        "mma.sync.aligned.m16n8k16.row.col.f32.f16.f16.f32 "
        "{%0,%1,%2,%3}, {%4,%5,%6,%7}, {%8,%9}, {%0,%1,%2,%3};"
        : "+f"(d[0]), "+f"(d[1]), "+f"(d[2]), "+f"(d[3])
        : "r"(a[0]), "r"(a[1]), "r"(a[2]), "r"(a[3]), "r"(b[0]), "r"(b[1]));
}

// ---------------- GEMM config ----------------
constexpr int BM = 128, BN = 128, BK = 32;       // BK in halves
constexpr int LDA = 40;                           // smem row stride (halves), padded

// ---------------- fp16 tensor-core GEMM: epi(A[M,K] @ B[N,K]^T + bias) ----------------
// GATHER=1: A row r = [objh[edges[2r]] | predh[r] | objh[edges[2r+1]]]  (K=1536)
// MODE 0: Ch[r,c] = relu(v)   (half output)
// MODE 1: Cf[r,c] += v        (float residual add)
// MODE 2: split by CTA column region (colBlock>>9): 0 -> atomicAdd pooled[s_idx];
//         1 -> outp store; 2 -> atomicAdd pooled[o_idx]   (relu applied)
// MODE 3: Cf[r,c] = relu(v)   (float output)
template <int GATHER, int MODE>
__global__ void __launch_bounds__(256, 2)
gemm_h(const __half* __restrict__ A, const __half* __restrict__ B,
       const float* __restrict__ bias,
       __half* __restrict__ Ch, float* __restrict__ Cf,
       int M, int N, int K,
       const __half* __restrict__ objh, const __half* __restrict__ predh,
       const int* __restrict__ edges,
       float* __restrict__ pooled, float* __restrict__ outp)
{
    __shared__ __align__(16) __half As[2][BM * LDA];
    __shared__ __align__(16) __half Bs[2][BN * LDA];

    const int tid = threadIdx.x;
    const int wid = tid >> 5, lane = tid & 31;
    const int wm = wid & 1;          // warp row (2)
    const int wn = wid >> 1;         // warp col (4)
    const int rowBlock = blockIdx.y * BM;
    const int colBlock = blockIdx.x * BN;

    // ---- loader mapping: each thread owns one A row-half and one B row-half ----
    const int lrow = tid >> 1;       // 0..127
    const int lhs  = (tid & 1) * 16; // 0 or 16 (halves within BK)

    const int gr  = rowBlock + lrow;
    const int grc = gr < M ? gr : (M - 1);
    const __half* arow = nullptr;
    const __half* asrc0 = nullptr;   // gather region pointers
    const __half* asrc1 = nullptr;
    const __half* asrc2 = nullptr;
    if (GATHER) {
        asrc0 = objh  + (size_t)__ldg(&edges[2 * grc])     * DIM;
        asrc1 = predh + (size_t)grc * DIM;
        asrc2 = objh  + (size_t)__ldg(&edges[2 * grc + 1]) * DIM;
    } else {
        arow = A + (size_t)grc * K;
    }
    const __half* brow = B + (size_t)(colBlock + lrow) * K;

    float acc[4][4][4];
#pragma unroll
    for (int i = 0; i < 4; i++)
#pragma unroll
        for (int j = 0; j < 4; j++)
#pragma unroll
            for (int q = 0; q < 4; q++) acc[i][j][q] = 0.f;

    const int nst = K >> 5;

    // ---- stage loader ----
    auto load_stage = [&](int i, int buf) {
        const int kb = (i << 5) + lhs;
        __half* adst = &As[buf][lrow * LDA + lhs];
        __half* bdst = &Bs[buf][lrow * LDA + lhs];
#pragma unroll
        for (int c = 0; c < 2; c++) {
            const int k = kb + c * 8;
            const __half* src;
            if (GATHER) {
                if (k < DIM)            src = asrc0 + k;
                else if (k < 2 * DIM)   src = asrc1 + (k - DIM);
                else                    src = asrc2 + (k - 2 * DIM);
            } else {
                src = arow + k;
            }
            cp16(adst + c * 8, src);
            cp16(bdst + c * 8, brow + k);
        }
        cp_commit();
    };

    load_stage(0, 0);

    const int lr = lane >> 2;
    const int lk = (lane & 3) * 2;

    for (int i = 0; i < nst; i++) {
        if (i + 1 < nst) load_stage(i + 1, (i + 1) & 1);
        if (i + 1 < nst) asm volatile("cp.async.wait_group 1;" ::: "memory");
        else             asm volatile("cp.async.wait_group 0;" ::: "memory");
        __syncthreads();

        const __half* Ab = &As[i & 1][(wm * 64 + lr) * LDA];
        const __half* Bb = &Bs[i & 1][(wn * 32 + lr) * LDA];
#pragma unroll
        for (int kk = 0; kk < 2; kk++) {
            const int k = kk * 16 + lk;
            uint32_t a[4][4], b[4][2];
#pragma unroll
            for (int mt = 0; mt < 4; mt++) {
                const __half* p = Ab + mt * 16 * LDA + k;
                a[mt][0] = *reinterpret_cast<const uint32_t*>(p);
                a[mt][1] = *reinterpret_cast<const uint32_t*>(p + 8 * LDA);
                a[mt][2] = *reinterpret_cast<const uint32_t*>(p + 8);
                a[mt][3] = *reinterpret_cast<const uint32_t*>(p + 8 * LDA + 8);
            }
#pragma unroll
            for (int nt = 0; nt < 4; nt++) {
                const __half* q = Bb + nt * 8 * LDA + k;
                b[nt][0] = *reinterpret_cast<const uint32_t*>(q);
                b[nt][1] = *reinterpret_cast<const uint32_t*>(q + 8);
            }
#pragma unroll
            for (int mt = 0; mt < 4; mt++)
#pragma unroll
                for (int nt = 0; nt < 4; nt++)
                    mma16816(acc[mt][nt], a[mt], b[nt]);
        }
        __syncthreads();
    }

    // ---- epilogue ----
    const int region = colBlock >> 9;   // for MODE 2 (CTA never straddles a 512 region)
#pragma unroll
    for (int mt = 0; mt < 4; mt++) {
        const int r0 = rowBlock + wm * 64 + mt * 16 + (lane >> 2);
        const int r1 = r0 + 8;
        const bool ok0 = r0 < M, ok1 = r1 < M;
        int idx0 = 0, idx1 = 0;
        if (MODE == 2) {
            if (region == 0) {
                if (ok0) idx0 = edges[2 * r0];
                if (ok1) idx1 = edges[2 * r1];
            } else if (region == 2) {
                if (ok0) idx0 = edges[2 * r0 + 1];
                if (ok1) idx1 = edges[2 * r1 + 1];
            }
        }
#pragma unroll
        for (int nt = 0; nt < 4; nt++) {
            const int c = colBlock + wn * 32 + nt * 8 + 2 * (lane & 3);
            const float bx = bias[c], by = bias[c + 1];
            float v00 = acc[mt][nt][0] + bx, v01 = acc[mt][nt][1] + by;
            float v10 = acc[mt][nt][2] + bx, v11 = acc[mt][nt][3] + by;
            if (MODE == 0 || MODE == 2 || MODE == 3) {
                v00 = fmaxf(v00, 0.f); v01 = fmaxf(v01, 0.f);
                v10 = fmaxf(v10, 0.f); v11 = fmaxf(v11, 0.f);
            }
            if (MODE == 0) {
                if (ok0) *reinterpret_cast<__half2*>(Ch + (size_t)r0 * N + c) = __floats2half2_rn(v00, v01);
                if (ok1) *reinterpret_cast<__half2*>(Ch + (size_t)r1 * N + c) = __floats2half2_rn(v10, v11);
            } else if (MODE == 3) {
                if (ok0) *reinterpret_cast<float2*>(Cf + (size_t)r0 * N + c) = make_float2(v00, v01);
                if (ok1) *reinterpret_cast<float2*>(Cf + (size_t)r1 * N + c) = make_float2(v10, v11);
            } else if (MODE == 1) {
                if (ok0) {
                    float2 o = *reinterpret_cast<const float2*>(Cf + (size_t)r0 * N + c);
                    *reinterpret_cast<float2*>(Cf + (size_t)r0 * N + c) = make_float2(o.x + v00, o.y + v01);
                }
                if (ok1) {
                    float2 o = *reinterpret_cast<const float2*>(Cf + (size_t)r1 * N + c);
                    *reinterpret_cast<float2*>(Cf + (size_t)r1 * N + c) = make_float2(o.x + v10, o.y + v11);
                }
            } else { // MODE 2
                const int cl = c & 511;
                if (region == 1) {
                    if (ok0) *reinterpret_cast<float2*>(outp + (size_t)r0 * DIM + cl) = make_float2(v00, v01);
                    if (ok1) *reinterpret_cast<float2*>(outp + (size_t)r1 * DIM + cl) = make_float2(v10, v11);
                } else {
                    if (ok0) {
                        atomicAdd(&pooled[(size_t)idx0 * DIM + cl],     v00);
                        atomicAdd(&pooled[(size_t)idx0 * DIM + cl + 1], v01);
                    }
                    if (ok1) {
                        atomicAdd(&pooled[(size_t)idx1 * DIM + cl],     v10);
                        atomicAdd(&pooled[(size_t)idx1 * DIM + cl + 1], v11);
                    }
                }
            }
        }
    }
}

// ---------------- small kernels ----------------
__global__ void f2h_kernel(const float4* __restrict__ src, uint2* __restrict__ dst, int n4) {
    int i = blockIdx.x * blockDim.x + threadIdx.x;
    if (i < n4) {
        float4 v = src[i];
        __half2 h0 = __floats2half2_rn(v.x, v.y);
        __half2 h1 = __floats2half2_rn(v.z, v.w);
        uint2 u;
        u.x = *reinterpret_cast<uint32_t*>(&h0);
        u.y = *reinterpret_cast<uint32_t*>(&h1);
        dst[i] = u;
    }
}

__global__ void zero_kernel(float* pooled, float* counts) {
    int i = blockIdx.x * blockDim.x + threadIdx.x;
    if (i < NOBJ * DIM) pooled[i] = 0.f;
    if (i < NOBJ) counts[i] = 0.f;
}

__global__ void count_kernel(const int* __restrict__ edges, float* counts) {
    int i = blockIdx.x * blockDim.x + threadIdx.x;
    if (i < NTRI) {
        atomicAdd(&counts[edges[2 * i]], 1.f);
        atomicAdd(&counts[edges[2 * i + 1]], 1.f);
    }
}

__global__ void normalize_kernel(const float* __restrict__ pooled,
                                 const float* __restrict__ counts,
                                 __half* __restrict__ poolh) {
    int i = blockIdx.x * blockDim.x + threadIdx.x;
    if (i < NOBJ * DIM) {
        float c = counts[i >> 9];
        poolh[i] = __float2half_rn(pooled[i] * (1.f / fmaxf(c, 1.f)));
    }
}

// ---------------- launcher ----------------
static inline void f2h(const float* src, __half* dst, size_t n) {
    int n4 = (int)(n / 4);
    f2h_kernel<<<(n4 + 255) / 256, 256>>>((const float4*)src, (uint2*)dst, n4);
}

extern "C" void kernel_launch(void* const* d_in, const int* in_sizes, int n_in,
                              void* d_out, int out_size)
{
    const float* objv    = (const float*)d_in[0];
    const float* predv   = (const float*)d_in[1];
    const int*   edges   = (const int*)  d_in[2];
    const float* W1      = (const float*)d_in[3];
    const float* b1      = (const float*)d_in[4];
    const float* W2      = (const float*)d_in[5];
    const float* b2      = (const float*)d_in[6];
    const float* V1      = (const float*)d_in[7];
    const float* c1      = (const float*)d_in[8];
    const float* V2      = (const float*)d_in[9];
    const float* c2      = (const float*)d_in[10];
    const float* P_obj   = (const float*)d_in[11];
    const float* pb_obj  = (const float*)d_in[12];
    const float* P_pred  = (const float*)d_in[13];
    const float* pb_pred = (const float*)d_in[14];

    __half *hh, *poolh, *gh, *objh, *predh, *w1h, *w2h, *v1h, *v2h, *poh, *pph;
    float *pooledp, *countsp;
    cudaGetSymbolAddress((void**)&hh,      g_hh);
    cudaGetSymbolAddress((void**)&pooledp, g_pooled);
    cudaGetSymbolAddress((void**)&poolh,   g_poolh);
    cudaGetSymbolAddress((void**)&gh,      g_gh);
    cudaGetSymbolAddress((void**)&countsp, g_counts);
    cudaGetSymbolAddress((void**)&objh,    g_objh);
    cudaGetSymbolAddress((void**)&predh,   g_predh);
    cudaGetSymbolAddress((void**)&w1h,     g_W1h);
    cudaGetSymbolAddress((void**)&w2h,     g_W2h);
    cudaGetSymbolAddress((void**)&v1h,     g_V1h);
    cudaGetSymbolAddress((void**)&v2h,     g_V2h);
    cudaGetSymbolAddress((void**)&poh,     g_Poh);
    cudaGetSymbolAddress((void**)&pph,     g_Pph);

    float* out_obj = (float*)d_out;
    float* out_p   = (float*)d_out + (size_t)NOBJ * DIM;

    // convert inputs/weights to fp16 (RN)
    f2h(objv,   objh,  (size_t)NOBJ * DIM);
    f2h(predv,  predh, (size_t)NTRI * DIM);
    f2h(W1,     w1h,   512 * 1536);
    f2h(W2,     w2h,   1536 * 512);
    f2h(V1,     v1h,   512 * 512);
    f2h(V2,     v2h,   512 * 512);
    f2h(P_obj,  poh,   512 * 512);
    f2h(P_pred, pph,   512 * 512);

    zero_kernel<<<(NOBJ * DIM + 255) / 256, 256>>>(pooledp, countsp);
    count_kernel<<<(NTRI + 255) / 256, 256>>>(edges, countsp);

    const int gMtri = (NTRI + BM - 1) / BM;   // 782
    const int gMobj = (NOBJ + BM - 1) / BM;   // 157

    // G1: h = relu([obj[s]|pred|obj[o]] @ W1^T + b1) -> half
    gemm_h<1, 0><<<dim3(512 / BN, gMtri), 256>>>(
        nullptr, w1h, b1, hh, nullptr, NTRI, 512, 1536,
        objh, predh, edges, nullptr, nullptr);

    // G2: new_t = relu(h @ W2^T + b2); split -> pooled atomics + out_p
    gemm_h<0, 2><<<dim3(1536 / BN, gMtri), 256>>>(
        hh, w2h, b2, nullptr, nullptr, NTRI, 1536, 512,
        nullptr, nullptr, edges, pooledp, out_p);

    // pooled /= max(counts,1) -> half
    normalize_kernel<<<(NOBJ * DIM + 255) / 256, 256>>>(pooledp, countsp, poolh);

    // G3: g = relu(pooled @ V1^T + c1) -> half
    gemm_h<0, 0><<<dim3(512 / BN, gMobj), 256>>>(
        poolh, v1h, c1, gh, nullptr, NOBJ, 512, 512,
        nullptr, nullptr, nullptr, nullptr, nullptr);

    // G4: out_obj = relu(g @ V2^T + c2) -> float
    gemm_h<0, 3><<<dim3(512 / BN, gMobj), 256>>>(
        gh, v2h, c2, nullptr, out_obj, NOBJ, 512, 512,
        nullptr, nullptr, nullptr, nullptr, nullptr);

    // G5: out_obj += obj @ P_obj^T + pb_obj
    gemm_h<0, 1><<<dim3(512 / BN, gMobj), 256>>>(
        objh, poh, pb_obj, nullptr, out_obj, NOBJ, 512, 512,
        nullptr, nullptr, nullptr, nullptr, nullptr);

    // G6: out_p += pred @ P_pred^T + pb_pred
    gemm_h<0, 1><<<dim3(512 / BN, gMtri), 256>>>(
        predh, pph, pb_pred, nullptr, out_p, NTRI, 512, 512,
        nullptr, nullptr, nullptr, nullptr, nullptr);
}